// round 4
// baseline (speedup 1.0000x reference)
#include <cuda_runtime.h>
#include <cuda_bf16.h>
#include <math.h>

#define H_DIM 2
#define L_LAYERS 4
#define R_RELS 16
#define B_BASES 8
#define N_NODES 1000000
#define E_EDGES 16000000

#define TILE_SHIFT 10
#define TILE_SIZE 1024
#define N_TILES ((N_NODES + TILE_SIZE - 1) / TILE_SIZE)   // 977
#define CAP 18432   // Poisson(16384) + 16 sigma

// ---- device scratch (allocation-free rule) --------------------------------
__device__ float2 g_x[N_NODES];
__device__ float2 g_h[N_NODES];
__device__ float2 g_skip[N_NODES];
__device__ int2   g_bin[N_TILES * CAP];   // 144 MB staging bins
__device__ int2   g_pay[E_EDGES];         // sorted payload {src|type<<20, norm}
__device__ int    g_sdst[E_EDGES];        // sorted dst
__device__ int    g_cursor[N_TILES];
__device__ int    g_row[N_TILES + 1];
__device__ float  g_W[L_LAYERS * R_RELS * 4];
__device__ float  g_acc;

// ---------------------------------------------------------------------------
__global__ void compute_weights_kernel(const float* __restrict__ V,
                                       const float* __restrict__ comp) {
    int tid = threadIdx.x;
    if (tid >= L_LAYERS * R_RELS) return;
    int l = tid / R_RELS, r = tid % R_RELS;
    float w0 = 0.f, w1 = 0.f, w2 = 0.f, w3 = 0.f;
    #pragma unroll
    for (int b = 0; b < B_BASES; b++) {
        float c = comp[(l * R_RELS + r) * B_BASES + b];
        const float* v = V + ((l * B_BASES + b) * 4);
        w0 += c * v[0]; w1 += c * v[1]; w2 += c * v[2]; w3 += c * v[3];
    }
    g_W[tid * 4 + 0] = w0; g_W[tid * 4 + 1] = w1;
    g_W[tid * 4 + 2] = w2; g_W[tid * 4 + 3] = w3;
}

// features -> x, skip; h = bias[0]; cursors = 0; acc = 0
__global__ void init_kernel(const float2* __restrict__ feat,
                            const float* __restrict__ bias) {
    int i = blockIdx.x * blockDim.x + threadIdx.x;
    if (i == 0) g_acc = 0.f;
    if (i < N_TILES) g_cursor[i] = 0;
    if (i >= N_NODES) return;
    float2 f = feat[i];
    g_x[i] = f;
    g_skip[i] = f;
    g_h[i] = make_float2(bias[0], bias[1]);
}

// ---- bin by dst tile (fixed-capacity bins, cursor atomics) ----------------
__global__ void binscatter_kernel(const int* __restrict__ src,
                                  const int* __restrict__ dst,
                                  const int* __restrict__ type,
                                  const float* __restrict__ norm) {
    int i = blockIdx.x * blockDim.x + threadIdx.x;
    if (i >= E_EDGES) return;
    int s  = src[i];
    int d  = dst[i];
    int t  = type[i];
    int nb = __float_as_int(norm[i]);
    int tile = d >> TILE_SHIFT;
    int dl   = d & (TILE_SIZE - 1);
    int pos = atomicAdd(&g_cursor[tile], 1);
    if (pos < CAP) {
        // pack dl into 8 spare bits of .x and 2 low mantissa bits of norm
        int px = s | (t << 20) | ((dl & 0xFF) << 24);
        int py = (nb & ~3) | (dl >> 8);
        g_bin[tile * CAP + pos] = make_int2(px, py);
    }
}

// ---- exclusive scan of tile counts (1 block) ------------------------------
__global__ void scan_kernel() {
    __shared__ int s[1024];
    int t = threadIdx.x;
    int v = (t < N_TILES) ? min(g_cursor[t], CAP) : 0;
    s[t] = v;
    __syncthreads();
    #pragma unroll
    for (int off = 1; off < 1024; off <<= 1) {
        int x = (t >= off) ? s[t - off] : 0;
        __syncthreads();
        s[t] += x;
        __syncthreads();
    }
    if (t < N_TILES) g_row[t] = s[t] - v;
    if (t == 0) g_row[N_TILES] = E_EDGES;
}

// ---- per-tile counting sort in smem; sequential global in/out -------------
__global__ void localsort_kernel() {
    extern __shared__ char sm[];
    int2* s_pay = (int2*)sm;                                   // CAP * 8
    unsigned short* s_dl = (unsigned short*)(sm + CAP * 8);    // CAP * 2
    int* cnt = (int*)(sm + CAP * 8 + CAP * 2);                 // 1024 * 4
    int* scn = cnt + 1024;                                     // 1024 * 4

    int t = blockIdx.x;
    int n = min(g_cursor[t], CAP);
    int row = g_row[t];
    const int2* bin = &g_bin[t * CAP];
    int tid = threadIdx.x;

    cnt[tid] = 0;
    __syncthreads();

    // pass 1: histogram of dst_local
    for (int i = tid; i < n; i += blockDim.x) {
        int2 p = bin[i];
        int dl = ((p.x >> 24) & 0xFF) | ((p.y & 3) << 8);
        atomicAdd(&cnt[dl], 1);
    }
    __syncthreads();

    // exclusive scan cnt -> cnt (as running cursors)
    int v = cnt[tid];
    scn[tid] = v;
    __syncthreads();
    #pragma unroll
    for (int off = 1; off < 1024; off <<= 1) {
        int x = (tid >= off) ? scn[tid - off] : 0;
        __syncthreads();
        scn[tid] += x;
        __syncthreads();
    }
    cnt[tid] = scn[tid] - v;
    __syncthreads();

    // pass 2: place into sorted smem position
    for (int i = tid; i < n; i += blockDim.x) {
        int2 p = bin[i];   // L2-hot (just read in pass 1)
        int dl = ((p.x >> 24) & 0xFF) | ((p.y & 3) << 8);
        int pos = atomicAdd(&cnt[dl], 1);
        s_pay[pos] = make_int2(p.x & 0x00FFFFFF, p.y & ~3);
        s_dl[pos] = (unsigned short)dl;
    }
    __syncthreads();

    // pass 3: sequential coalesced write-out
    int nbase = t << TILE_SHIFT;
    for (int i = tid; i < n; i += blockDim.x) {
        g_pay[row + i] = s_pay[i];
        g_sdst[row + i] = nbase + s_dl[i];
    }
}

// ---- layer: edge-parallel, warp-segmented reduction on sorted dst ---------
__global__ void layer_kernel(int l, const float2* __restrict__ xin) {
    __shared__ float sW[R_RELS * 4];
    if (threadIdx.x < R_RELS * 4)
        sW[threadIdx.x] = g_W[l * R_RELS * 4 + threadIdx.x];
    __syncthreads();

    int e = blockIdx.x * blockDim.x + threadIdx.x;
    if (e >= E_EDGES) return;

    int d = g_sdst[e];
    int2 p = g_pay[e];
    int src = p.x & 0xFFFFF;
    int typ = (p.x >> 20) & 0xF;
    float nrm = __int_as_float(p.y);
    float2 xs = __ldg(&xin[src]);
    const float* w = &sW[typ * 4];
    float mx = (xs.x * w[0] + xs.y * w[2]) * nrm;
    float my = (xs.x * w[1] + xs.y * w[3]) * nrm;

    // suffix segmented sum over sorted keys within warp
    int lane = threadIdx.x & 31;
    #pragma unroll
    for (int off = 1; off < 32; off <<= 1) {
        float ax = __shfl_down_sync(0xFFFFFFFFu, mx, off);
        float ay = __shfl_down_sync(0xFFFFFFFFu, my, off);
        int   dd = __shfl_down_sync(0xFFFFFFFFu, d, off);
        if (lane + off < 32 && dd == d) { mx += ax; my += ay; }
    }
    int dprev = __shfl_up_sync(0xFFFFFFFFu, d, 1);
    bool head = (lane == 0) || (dprev != d);
    if (head) atomicAdd(&g_h[d], make_float2(mx, my));
}

// ---- epilogue: relu/skip -> x ; re-init h with next bias ------------------
__global__ void epi_kernel(int l, const float* __restrict__ bias) {
    int i = blockIdx.x * blockDim.x + threadIdx.x;
    if (i >= N_NODES) return;
    float2 h = g_h[i];
    if (l < L_LAYERS - 1) {
        h.x = fmaxf(h.x, 0.f);
        h.y = fmaxf(h.y, 0.f);
    }
    if (l & 1) {
        float2 sk = g_skip[i];
        h.x += sk.x; h.y += sk.y;
        g_skip[i] = make_float2(h.x, h.y);
    }
    g_x[i] = h;
    if (l < L_LAYERS - 1)
        g_h[i] = make_float2(bias[2 * (l + 1)], bias[2 * (l + 1) + 1]);
}

// ---- final dot + sigmoid --------------------------------------------------
__global__ void dot_kernel(const float4* __restrict__ w4) {
    const float4* x4 = (const float4*)g_x;
    const int total4 = (N_NODES * H_DIM) / 4;
    float sum = 0.f;
    for (int i = blockIdx.x * blockDim.x + threadIdx.x; i < total4;
         i += gridDim.x * blockDim.x) {
        float4 a = x4[i];
        float4 b = w4[i];
        sum += a.x * b.x + a.y * b.y + a.z * b.z + a.w * b.w;
    }
    #pragma unroll
    for (int off = 16; off > 0; off >>= 1)
        sum += __shfl_down_sync(0xFFFFFFFFu, sum, off);
    __shared__ float ws[8];
    int lane = threadIdx.x & 31, wid = threadIdx.x >> 5;
    if (lane == 0) ws[wid] = sum;
    __syncthreads();
    if (wid == 0) {
        sum = (lane < (blockDim.x >> 5)) ? ws[lane] : 0.f;
        #pragma unroll
        for (int off = 4; off > 0; off >>= 1)
            sum += __shfl_down_sync(0xFFFFFFFFu, sum, off);
        if (lane == 0) atomicAdd(&g_acc, sum);
    }
}

__global__ void finalize_kernel(const float* __restrict__ b_mlp,
                                float* __restrict__ out) {
    float logit = g_acc + b_mlp[0];
    out[0] = 1.f / (1.f + expf(-logit));
}

// ---------------------------------------------------------------------------
extern "C" void kernel_launch(void* const* d_in, const int* in_sizes, int n_in,
                              void* d_out, int out_size) {
    const float* features  = (const float*)d_in[0];
    const float* norm      = (const float*)d_in[1];
    const float* V         = (const float*)d_in[2];
    const float* comp      = (const float*)d_in[3];
    const float* bias      = (const float*)d_in[4];
    const float* w_mlp     = (const float*)d_in[5];
    const float* b_mlp     = (const float*)d_in[6];
    const int*   edge_src  = (const int*)d_in[7];
    const int*   edge_dst  = (const int*)d_in[8];
    const int*   edge_type = (const int*)d_in[9];
    float*       out       = (float*)d_out;

    const int TB = 256;
    const int node_blocks = (N_NODES + TB - 1) / TB;
    const int edge_blocks = (E_EDGES + TB - 1) / TB;   // 62500, exact

    // opt-in to large dynamic smem for the per-tile sort
    const int sort_smem = CAP * 8 + CAP * 2 + 2048 * 4;   // 192,512 B
    static bool attr_set = false;
    if (!attr_set) {
        cudaFuncSetAttribute(localsort_kernel,
                             cudaFuncAttributeMaxDynamicSharedMemorySize,
                             sort_smem);
        attr_set = true;
    }

    compute_weights_kernel<<<1, 64>>>(V, comp);
    init_kernel<<<node_blocks, TB>>>((const float2*)features, bias);

    binscatter_kernel<<<edge_blocks, TB>>>(edge_src, edge_dst,
                                           edge_type, norm);
    scan_kernel<<<1, 1024>>>();
    localsort_kernel<<<N_TILES, 1024, sort_smem>>>();

    void* px = nullptr;
    cudaGetSymbolAddress(&px, g_x);
    const float2* fx = (const float2*)px;

    for (int l = 0; l < L_LAYERS; l++) {
        layer_kernel<<<edge_blocks, TB>>>(l, fx);
        epi_kernel<<<node_blocks, TB>>>(l, bias);
    }

    dot_kernel<<<1024, TB>>>((const float4*)w_mlp);
    finalize_kernel<<<1, 1>>>(b_mlp, out);
}

// round 5
// speedup vs baseline: 3.2759x; 3.2759x over previous
#include <cuda_runtime.h>
#include <cuda_bf16.h>
#include <math.h>

#define H_DIM 2
#define L_LAYERS 4
#define R_RELS 16
#define B_BASES 8
#define N_NODES 1000000
#define E_EDGES 16000000
#define EPT 8                     // edges per thread
#define ETHREADS (E_EDGES / EPT)  // 2,000,000

// ---- device scratch (allocation-free rule) --------------------------------
__device__ float2 g_x[N_NODES];
__device__ float2 g_h[N_NODES];
__device__ float2 g_skip[N_NODES];
__device__ float  g_W[L_LAYERS * R_RELS * 4];
__device__ float  g_acc;

// ---------------------------------------------------------------------------
__global__ void compute_weights_kernel(const float* __restrict__ V,
                                       const float* __restrict__ comp) {
    int tid = threadIdx.x;
    if (tid >= L_LAYERS * R_RELS) return;
    int l = tid / R_RELS, r = tid % R_RELS;
    float w0 = 0.f, w1 = 0.f, w2 = 0.f, w3 = 0.f;
    #pragma unroll
    for (int b = 0; b < B_BASES; b++) {
        float c = comp[(l * R_RELS + r) * B_BASES + b];
        const float* v = V + ((l * B_BASES + b) * 4);
        w0 += c * v[0]; w1 += c * v[1]; w2 += c * v[2]; w3 += c * v[3];
    }
    g_W[tid * 4 + 0] = w0; g_W[tid * 4 + 1] = w1;
    g_W[tid * 4 + 2] = w2; g_W[tid * 4 + 3] = w3;
}

// features -> x, skip; h = 0; acc = 0
__global__ void init_kernel(const float2* __restrict__ feat) {
    int i = blockIdx.x * blockDim.x + threadIdx.x;
    if (i == 0) g_acc = 0.f;
    if (i >= N_NODES) return;
    float2 f = feat[i];
    g_x[i] = f;
    g_skip[i] = f;
    g_h[i] = make_float2(0.f, 0.f);
}

// ---------------------------------------------------------------------------
// Edge kernel: 8 edges/thread; front-batch all streaming loads and gathers
// to maximize MLP, then do the math, then fire the 8 float2 REDs.
__global__ void __launch_bounds__(256) edge_kernel(
        const int4* __restrict__ src4,
        const int4* __restrict__ dst4,
        const int4* __restrict__ type4,
        const float4* __restrict__ norm4,
        int l) {
    __shared__ float sW[R_RELS * 4];
    if (threadIdx.x < R_RELS * 4)
        sW[threadIdx.x] = g_W[l * R_RELS * 4 + threadIdx.x];
    __syncthreads();

    int i = blockIdx.x * blockDim.x + threadIdx.x;
    if (i >= ETHREADS) return;
    int q = i * 2;   // index into the int4 arrays (2 int4 = 8 edges)

    // streaming loads (8 sector-dense loads, all independent)
    int4   s0 = src4[q],  s1 = src4[q + 1];
    int4   d0 = dst4[q],  d1 = dst4[q + 1];
    int4   t0 = type4[q], t1 = type4[q + 1];
    float4 n0 = norm4[q], n1 = norm4[q + 1];

    int   ss[EPT] = {s0.x, s0.y, s0.z, s0.w, s1.x, s1.y, s1.z, s1.w};
    int   dd[EPT] = {d0.x, d0.y, d0.z, d0.w, d1.x, d1.y, d1.z, d1.w};
    int   tt[EPT] = {t0.x, t0.y, t0.z, t0.w, t1.x, t1.y, t1.z, t1.w};
    float nn[EPT] = {n0.x, n0.y, n0.z, n0.w, n1.x, n1.y, n1.z, n1.w};

    // gathers (8 independent random loads in flight)
    float2 xs[EPT];
    #pragma unroll
    for (int k = 0; k < EPT; k++) xs[k] = __ldg(&g_x[ss[k]]);

    // math + scatter
    #pragma unroll
    for (int k = 0; k < EPT; k++) {
        const float* w = &sW[tt[k] * 4];
        float mx = (xs[k].x * w[0] + xs[k].y * w[2]) * nn[k];
        float my = (xs[k].x * w[1] + xs[k].y * w[3]) * nn[k];
        atomicAdd(&g_h[dd[k]], make_float2(mx, my));
    }
}

// ---------------------------------------------------------------------------
// Epilogue: x = f(h + bias); h <- 0 for next layer.
__global__ void epi_kernel(int l, const float* __restrict__ bias) {
    int i = blockIdx.x * blockDim.x + threadIdx.x;
    if (i >= N_NODES) return;
    float2 h = g_h[i];
    h.x += __ldg(&bias[2 * l]);
    h.y += __ldg(&bias[2 * l + 1]);
    if (l < L_LAYERS - 1) {
        h.x = fmaxf(h.x, 0.f);
        h.y = fmaxf(h.y, 0.f);
    }
    if (l & 1) {
        float2 sk = g_skip[i];
        h.x += sk.x; h.y += sk.y;
        g_skip[i] = h;
    }
    g_x[i] = h;
    if (l < L_LAYERS - 1) g_h[i] = make_float2(0.f, 0.f);
}

// ---------------------------------------------------------------------------
__global__ void dot_kernel(const float4* __restrict__ w4) {
    const float4* x4 = (const float4*)g_x;
    const int total4 = (N_NODES * H_DIM) / 4;
    float sum = 0.f;
    for (int i = blockIdx.x * blockDim.x + threadIdx.x; i < total4;
         i += gridDim.x * blockDim.x) {
        float4 a = x4[i];
        float4 b = w4[i];
        sum += a.x * b.x + a.y * b.y + a.z * b.z + a.w * b.w;
    }
    #pragma unroll
    for (int off = 16; off > 0; off >>= 1)
        sum += __shfl_down_sync(0xFFFFFFFFu, sum, off);
    __shared__ float ws[8];
    int lane = threadIdx.x & 31, wid = threadIdx.x >> 5;
    if (lane == 0) ws[wid] = sum;
    __syncthreads();
    if (wid == 0) {
        sum = (lane < (blockDim.x >> 5)) ? ws[lane] : 0.f;
        #pragma unroll
        for (int off = 4; off > 0; off >>= 1)
            sum += __shfl_down_sync(0xFFFFFFFFu, sum, off);
        if (lane == 0) atomicAdd(&g_acc, sum);
    }
}

__global__ void finalize_kernel(const float* __restrict__ b_mlp,
                                float* __restrict__ out) {
    float logit = g_acc + b_mlp[0];
    out[0] = 1.f / (1.f + expf(-logit));
}

// ---------------------------------------------------------------------------
extern "C" void kernel_launch(void* const* d_in, const int* in_sizes, int n_in,
                              void* d_out, int out_size) {
    const float* features  = (const float*)d_in[0];
    const float* norm      = (const float*)d_in[1];
    const float* V         = (const float*)d_in[2];
    const float* comp      = (const float*)d_in[3];
    const float* bias      = (const float*)d_in[4];
    const float* w_mlp     = (const float*)d_in[5];
    const float* b_mlp     = (const float*)d_in[6];
    const int*   edge_src  = (const int*)d_in[7];
    const int*   edge_dst  = (const int*)d_in[8];
    const int*   edge_type = (const int*)d_in[9];
    float*       out       = (float*)d_out;

    const int TB = 256;
    const int node_blocks = (N_NODES + TB - 1) / TB;
    const int edge_blocks = (ETHREADS + TB - 1) / TB;   // 7813

    compute_weights_kernel<<<1, 64>>>(V, comp);
    init_kernel<<<node_blocks, TB>>>((const float2*)features);

    for (int l = 0; l < L_LAYERS; l++) {
        edge_kernel<<<edge_blocks, TB>>>((const int4*)edge_src,
                                         (const int4*)edge_dst,
                                         (const int4*)edge_type,
                                         (const float4*)norm, l);
        epi_kernel<<<node_blocks, TB>>>(l, bias);
    }

    dot_kernel<<<1024, TB>>>((const float4*)w_mlp);
    finalize_kernel<<<1, 1>>>(b_mlp, out);
}